// round 12
// baseline (speedup 1.0000x reference)
#include <cuda_runtime.h>
#include <cstdint>

// ChamferDistance: B=4, N=8192, C=3 — uniform-grid nearest-neighbor version.
// loss = sum_b [ mean_i min_j d2(p1_i,p2_j) + mean_j min_i d2(...) ]
//
// 8 grids (4 batches x 2 sets), 32^3 cells, h=0.25 over [-4,4] (clamped).
// Counting sort per grid, then each query ring-searches the OPPOSITE grid
// outward, stopping when best <= (R*h)^2 (cells at Chebyshev ring K hold
// points >= (K-1)*h away; clamped points are farther -> bound stays valid).
// Deterministic: scatter order varies (atomic cursors) but min over any
// candidate order is exact; per-query results land in slots keyed by the
// ORIGINAL index (carried in .w) and are summed in fixed order.

constexpr int B_    = 4;
constexpr int N_    = 8192;
constexpr int NGRID = 8;                 // gid = b*2 + s  (s=0: p1, s=1: p2)
constexpr int G     = 32;
constexpr int CELLS = G * G * G;         // 32768
constexpr float H    = 0.25f;
constexpr float ORG  = -4.0f;
constexpr float INVH = 4.0f;
constexpr int NSLOT = NGRID * N_;        // 65536
constexpr int CBLK  = 64;

__device__ int    g_cnt[NGRID][CELLS];
__device__ int2   g_rng[NGRID][CELLS];   // {start, count}
__device__ int    g_cur[NGRID][CELLS];
__device__ float4 g_pts[NGRID][N_];      // sorted points, .w = original index
__device__ float  g_dist[NSLOT];         // per-query min d2, slot = gid*N + orig
__device__ float  g_part[CBLK];
__device__ unsigned int g_done = 0;

__device__ __forceinline__ int cellof(float v) {
    int i = (int)floorf((v - ORG) * INVH);
    return i < 0 ? 0 : (i > G - 1 ? G - 1 : i);
}
__device__ __forceinline__ const float* point_ptr(const float* p1, const float* p2,
                                                  int gid, int i) {
    const int b = gid >> 1, s = gid & 1;
    return (s ? p2 : p1) + ((size_t)b * N_ + i) * 3;
}

// ---- 1. zero histogram ------------------------------------------------
__global__ __launch_bounds__(256)
void k_zero()
{
    int idx = blockIdx.x * 256 + threadIdx.x;          // 65536 threads
    int* flat = &g_cnt[0][0];
    #pragma unroll
    for (int k = 0; k < NGRID * CELLS / 65536; k++)    // 4 per thread
        flat[idx + k * 65536] = 0;
}

// ---- 2. histogram -----------------------------------------------------
__global__ __launch_bounds__(256)
void k_hist(const float* __restrict__ p1, const float* __restrict__ p2)
{
    const int idx = blockIdx.x * 256 + threadIdx.x;    // 65536
    const int gid = idx >> 13, i = idx & (N_ - 1);
    const float* p = point_ptr(p1, p2, gid, i);
    const int c = (cellof(p[2]) * G + cellof(p[1])) * G + cellof(p[0]);
    atomicAdd(&g_cnt[gid][c], 1);
}

// ---- 3. exclusive scan per grid --------------------------------------
__global__ __launch_bounds__(1024)
void k_scan()
{
    const int gid = blockIdx.x;            // 8 blocks
    const int tid = threadIdx.x;           // 1024 threads, 32 cells each
    __shared__ int ssum[1024];

    const int base = tid * 32;
    int s = 0;
    for (int j = 0; j < 32; j++) s += g_cnt[gid][base + j];
    ssum[tid] = s;
    __syncthreads();
    for (int off = 1; off < 1024; off <<= 1) {
        int v = (tid >= off) ? ssum[tid - off] : 0;
        __syncthreads();
        ssum[tid] += v;
        __syncthreads();
    }
    int run = ssum[tid] - s;               // exclusive prefix for this chunk
    for (int j = 0; j < 32; j++) {
        const int c = base + j;
        const int n = g_cnt[gid][c];
        g_rng[gid][c] = make_int2(run, n);
        g_cur[gid][c] = run;
        run += n;
    }
}

// ---- 4. scatter -------------------------------------------------------
__global__ __launch_bounds__(256)
void k_scatter(const float* __restrict__ p1, const float* __restrict__ p2)
{
    const int idx = blockIdx.x * 256 + threadIdx.x;    // 65536
    const int gid = idx >> 13, i = idx & (N_ - 1);
    const float* p = point_ptr(p1, p2, gid, i);
    const float x = p[0], y = p[1], z = p[2];
    const int c = (cellof(z) * G + cellof(y)) * G + cellof(x);
    const int pos = atomicAdd(&g_cur[gid][c], 1);
    g_pts[gid][pos] = make_float4(x, y, z, __int_as_float(i));
}

// ---- 5. ring-search query --------------------------------------------
__global__ __launch_bounds__(256)
void k_query()
{
    const int idx = blockIdx.x * 256 + threadIdx.x;    // 65536
    const int gid = idx >> 13, i = idx & (N_ - 1);
    const int og  = gid ^ 1;                            // opposite set, same batch

    const float4 qp = g_pts[gid][i];                    // sorted -> coherent warps
    const float qx = qp.x, qy = qp.y, qz = qp.z;
    const int cx = cellof(qx), cy = cellof(qy), cz = cellof(qz);

    const int2*   __restrict__ rng = g_rng[og];
    const float4* __restrict__ pts = g_pts[og];

    float best = 1e30f;
    for (int R = 0; R < G; R++) {
        // shell: cells with Chebyshev distance exactly R
        for (int dz = -R; dz <= R; dz++) {
            const int z = cz + dz;
            if ((unsigned)z >= (unsigned)G) continue;
            const bool zedge = (dz == -R) | (dz == R);
            for (int dy = -R; dy <= R; dy++) {
                const int y = cy + dy;
                if ((unsigned)y >= (unsigned)G) continue;
                const bool edge = zedge | (dy == -R) | (dy == R);
                const int step = (edge || R == 0) ? 1 : 2 * R;
                for (int dx = -R; dx <= R; dx += step) {
                    const int x = cx + dx;
                    if ((unsigned)x >= (unsigned)G) continue;
                    const int2 rg = rng[(z * G + y) * G + x];
                    for (int t = rg.x; t < rg.x + rg.y; t++) {
                        const float4 pt = pts[t];
                        const float ax = qx - pt.x;
                        const float ay = qy - pt.y;
                        const float az = qz - pt.z;
                        float d = ax * ax;
                        d = fmaf(ay, ay, d);
                        d = fmaf(az, az, d);
                        best = fminf(best, d);
                    }
                }
            }
        }
        const float bound = (float)R * H;
        if (best <= bound * bound) break;
    }

    const int orig = __float_as_int(qp.w);
    g_dist[gid * N_ + orig] = best;        // one writer per slot, plain store
}

// ---- 6. fixed-order combine ------------------------------------------
__global__ __launch_bounds__(256)
void k_combine(float* __restrict__ out)
{
    const int tid = threadIdx.x;
    float s = 0.0f;
    #pragma unroll
    for (int k = 0; k < NSLOT / (CBLK * 256); k++)      // 4 per thread
        s += g_dist[blockIdx.x * (NSLOT / CBLK) + k * 256 + tid];

    #pragma unroll
    for (int o = 16; o > 0; o >>= 1)
        s += __shfl_down_sync(0xffffffffu, s, o);
    __shared__ float red[8];
    __shared__ bool  amLast;
    if ((tid & 31) == 0) red[tid >> 5] = s;
    __syncthreads();
    if (tid == 0) {
        float bs = 0.0f;
        #pragma unroll
        for (int wi = 0; wi < 8; wi++) bs += red[wi];
        g_part[blockIdx.x] = bs;
        __threadfence();
        amLast = (atomicAdd(&g_done, 1u) == CBLK - 1);
    }
    __syncthreads();

    if (amLast && tid < 32) {
        float v = g_part[tid] + g_part[tid + 32];
        #pragma unroll
        for (int o = 16; o > 0; o >>= 1)
            v += __shfl_down_sync(0xffffffffu, v, o);
        if (tid == 0) {
            out[0] = v * (1.0f / (float)N_);
            g_done = 0;   // reset for next graph replay
        }
    }
}

extern "C" void kernel_launch(void* const* d_in, const int* in_sizes, int n_in,
                              void* d_out, int out_size)
{
    const float* points1 = (const float*)d_in[0];
    const float* points2 = (const float*)d_in[1];
    float* out = (float*)d_out;

    k_zero   <<<256, 256>>>();
    k_hist   <<<256, 256>>>(points1, points2);
    k_scan   <<<NGRID, 1024>>>();
    k_scatter<<<256, 256>>>(points1, points2);
    k_query  <<<256, 256>>>();
    k_combine<<<CBLK, 256>>>(out);
}

// round 13
// speedup vs baseline: 5.2768x; 5.2768x over previous
#include <cuda_runtime.h>
#include <cstdint>

// ChamferDistance: B=4, N=8192, C=3 — uniform-grid NN, round 2.
// G=16 (h=0.5) + per-cell lower-bound pruning + tight per-query stop bound.
//
// 8 grids (4 batches x 2 sets). Counting sort, then each sorted query
// ring-searches the opposite grid; a cell is scanned only if its box
// lower-bound distance beats the current best; rings stop when
// best <= (m + R*h)^2 with m = distance from q to its own cell's nearest
// face. Deterministic: min is exact under candidate reordering; results
// keyed by original index; final sum in fixed order.

constexpr int B_    = 4;
constexpr int N_    = 8192;
constexpr int NGRID = 8;                 // gid = b*2 + s (s=0: p1, s=1: p2)
constexpr int G     = 16;
constexpr int CELLS = G * G * G;         // 4096
constexpr float H    = 0.5f;
constexpr float ORG  = -4.0f;
constexpr float INVH = 2.0f;
constexpr int NSLOT = NGRID * N_;        // 65536
constexpr int CBLK  = 64;

__device__ int    g_cnt[NGRID][CELLS];
__device__ int2   g_rng[NGRID][CELLS];   // {start, count}
__device__ int    g_cur[NGRID][CELLS];
__device__ float4 g_pts[NGRID][N_];      // sorted points, .w = original index
__device__ float  g_dist[NSLOT];
__device__ float  g_part[CBLK];
__device__ unsigned int g_done = 0;

__device__ __forceinline__ int cellof(float v) {
    int i = (int)floorf((v - ORG) * INVH);
    return i < 0 ? 0 : (i > G - 1 ? G - 1 : i);
}
__device__ __forceinline__ const float* point_ptr(const float* p1, const float* p2,
                                                  int gid, int i) {
    const int b = gid >> 1, s = gid & 1;
    return (s ? p2 : p1) + ((size_t)b * N_ + i) * 3;
}

// ---- 1. zero histograms ----------------------------------------------
__global__ __launch_bounds__(256)
void k_zero()
{
    const int idx = blockIdx.x * 256 + threadIdx.x;   // 32768 threads
    (&g_cnt[0][0])[idx] = 0;
}

// ---- 2. histogram -----------------------------------------------------
__global__ __launch_bounds__(256)
void k_hist(const float* __restrict__ p1, const float* __restrict__ p2)
{
    const int idx = blockIdx.x * 256 + threadIdx.x;   // 65536
    const int gid = idx >> 13, i = idx & (N_ - 1);
    const float* p = point_ptr(p1, p2, gid, i);
    const int c = (cellof(p[2]) * G + cellof(p[1])) * G + cellof(p[0]);
    atomicAdd(&g_cnt[gid][c], 1);
}

// ---- 3. exclusive scan per grid (4096 cells, 1024 thr x 4) -----------
__global__ __launch_bounds__(1024)
void k_scan()
{
    const int gid = blockIdx.x;            // 8 blocks
    const int tid = threadIdx.x;
    __shared__ int ssum[1024];

    const int base = tid * 4;
    int s = 0;
    #pragma unroll
    for (int j = 0; j < 4; j++) s += g_cnt[gid][base + j];
    ssum[tid] = s;
    __syncthreads();
    for (int off = 1; off < 1024; off <<= 1) {
        int v = (tid >= off) ? ssum[tid - off] : 0;
        __syncthreads();
        ssum[tid] += v;
        __syncthreads();
    }
    int run = ssum[tid] - s;
    #pragma unroll
    for (int j = 0; j < 4; j++) {
        const int c = base + j;
        const int n = g_cnt[gid][c];
        g_rng[gid][c] = make_int2(run, n);
        g_cur[gid][c] = run;
        run += n;
    }
}

// ---- 4. scatter -------------------------------------------------------
__global__ __launch_bounds__(256)
void k_scatter(const float* __restrict__ p1, const float* __restrict__ p2)
{
    const int idx = blockIdx.x * 256 + threadIdx.x;   // 65536
    const int gid = idx >> 13, i = idx & (N_ - 1);
    const float* p = point_ptr(p1, p2, gid, i);
    const float x = p[0], y = p[1], z = p[2];
    const int c = (cellof(z) * G + cellof(y)) * G + cellof(x);
    const int pos = atomicAdd(&g_cur[gid][c], 1);
    g_pts[gid][pos] = make_float4(x, y, z, __int_as_float(i));
}

// scan one cell's point list against (qx,qy,qz); unroll 2 for MLP
__device__ __forceinline__ float scan_cell(const float4* __restrict__ pts,
                                           int2 rg, float qx, float qy, float qz,
                                           float best)
{
    int t = rg.x;
    const int e = rg.x + rg.y;
    float b0 = best, b1 = 1e30f;
    for (; t + 1 < e; t += 2) {
        const float4 A = pts[t];
        const float4 Bp = pts[t + 1];
        const float ax = qx - A.x, ay = qy - A.y, az = qz - A.z;
        const float bx = qx - Bp.x, by = qy - Bp.y, bz = qz - Bp.z;
        float d0 = ax * ax; d0 = fmaf(ay, ay, d0); d0 = fmaf(az, az, d0);
        float d1 = bx * bx; d1 = fmaf(by, by, d1); d1 = fmaf(bz, bz, d1);
        b0 = fminf(b0, d0);
        b1 = fminf(b1, d1);
    }
    if (t < e) {
        const float4 A = pts[t];
        const float ax = qx - A.x, ay = qy - A.y, az = qz - A.z;
        float d0 = ax * ax; d0 = fmaf(ay, ay, d0); d0 = fmaf(az, az, d0);
        b0 = fminf(b0, d0);
    }
    return fminf(b0, b1);
}

// ---- 5. pruned ring-search query -------------------------------------
__global__ __launch_bounds__(256)
void k_query()
{
    const int idx = blockIdx.x * 256 + threadIdx.x;   // 65536
    const int gid = idx >> 13, i = idx & (N_ - 1);
    const int og  = gid ^ 1;

    const float4 qp = g_pts[gid][i];                  // sorted -> coherent warps
    const float qx = qp.x, qy = qp.y, qz = qp.z;
    const int cx = cellof(qx), cy = cellof(qy), cz = cellof(qz);

    // margin to own cell's nearest face (clamped points -> 0, conservative)
    const float lox = ORG + cx * H, loy = ORG + cy * H, loz = ORG + cz * H;
    float m = fminf(fminf(qx - lox, lox + H - qx),
             fminf(fminf(qy - loy, loy + H - qy),
                   fminf(qz - loz, loz + H - qz)));
    m = fmaxf(m, 0.0f);

    const int2*   __restrict__ rng = g_rng[og];
    const float4* __restrict__ pts = g_pts[og];

    float best = 1e30f;
    for (int R = 0; R < G; R++) {
        if (R == 0) {
            best = scan_cell(pts, rng[(cz * G + cy) * G + cx], qx, qy, qz, best);
        } else {
            for (int dz = -R; dz <= R; dz++) {
                const int z = cz + dz;
                if ((unsigned)z >= (unsigned)G) continue;
                const bool zedge = (dz == -R) | (dz == R);
                // per-axis z lower bound
                const float zlo = ORG + z * H;
                const float dzb = fmaxf(fmaxf(zlo - qz, qz - zlo - H), 0.0f);
                const float dz2 = dzb * dzb;
                if (dz2 >= best) continue;
                for (int dy = -R; dy <= R; dy++) {
                    const int y = cy + dy;
                    if ((unsigned)y >= (unsigned)G) continue;
                    const float ylo = ORG + y * H;
                    const float dyb = fmaxf(fmaxf(ylo - qy, qy - ylo - H), 0.0f);
                    const float dzy2 = fmaf(dyb, dyb, dz2);
                    if (dzy2 >= best) continue;
                    const bool edge = zedge | (dy == -R) | (dy == R);
                    const int step = edge ? 1 : 2 * R;
                    for (int dx = -R; dx <= R; dx += step) {
                        const int x = cx + dx;
                        if ((unsigned)x >= (unsigned)G) continue;
                        const float xlo = ORG + x * H;
                        const float dxb = fmaxf(fmaxf(xlo - qx, qx - xlo - H), 0.0f);
                        const float lb2 = fmaf(dxb, dxb, dzy2);
                        if (lb2 >= best) continue;          // box-prune the cell
                        const int2 rg = rng[(z * G + y) * G + x];
                        if (rg.y == 0) continue;
                        best = scan_cell(pts, rg, qx, qy, qz, best);
                    }
                }
            }
        }
        const float bound = m + (float)R * H;     // unvisited cells >= this far
        if (best <= bound * bound) break;
    }

    const int orig = __float_as_int(qp.w);
    g_dist[gid * N_ + orig] = best;               // one writer per slot
}

// ---- 6. fixed-order combine ------------------------------------------
__global__ __launch_bounds__(256)
void k_combine(float* __restrict__ out)
{
    const int tid = threadIdx.x;
    float s = 0.0f;
    #pragma unroll
    for (int k = 0; k < NSLOT / (CBLK * 256); k++)
        s += g_dist[blockIdx.x * (NSLOT / CBLK) + k * 256 + tid];

    #pragma unroll
    for (int o = 16; o > 0; o >>= 1)
        s += __shfl_down_sync(0xffffffffu, s, o);
    __shared__ float red[8];
    __shared__ bool  amLast;
    if ((tid & 31) == 0) red[tid >> 5] = s;
    __syncthreads();
    if (tid == 0) {
        float bs = 0.0f;
        #pragma unroll
        for (int wi = 0; wi < 8; wi++) bs += red[wi];
        g_part[blockIdx.x] = bs;
        __threadfence();
        amLast = (atomicAdd(&g_done, 1u) == CBLK - 1);
    }
    __syncthreads();

    if (amLast && tid < 32) {
        float v = g_part[tid] + g_part[tid + 32];
        #pragma unroll
        for (int o = 16; o > 0; o >>= 1)
            v += __shfl_down_sync(0xffffffffu, v, o);
        if (tid == 0) {
            out[0] = v * (1.0f / (float)N_);
            g_done = 0;   // reset for next graph replay
        }
    }
}

extern "C" void kernel_launch(void* const* d_in, const int* in_sizes, int n_in,
                              void* d_out, int out_size)
{
    const float* points1 = (const float*)d_in[0];
    const float* points2 = (const float*)d_in[1];
    float* out = (float*)d_out;

    k_zero   <<<CELLS * NGRID / 256, 256>>>();
    k_hist   <<<256, 256>>>(points1, points2);
    k_scan   <<<NGRID, 1024>>>();
    k_scatter<<<256, 256>>>(points1, points2);
    k_query  <<<256, 256>>>();
    k_combine<<<CBLK, 256>>>(out);
}